// round 11
// baseline (speedup 1.0000x reference)
#include <cuda_runtime.h>
#include <cuda_bf16.h>
#include <math.h>
#include <stdint.h>

#define TIMESTEPS 1000
#define NB 2048
#define NPER 64
#define NATOMS (NB*NPER)
#define NODE_DIM 64
#define HID 128
#define NSP 100
#define BA 128            // atoms per species tile
#define NTILES (NATOMS/BA)
#define SGRID 296         // persistent species grid (148 SMs x 2)

__device__ double g_mse;
__device__ double g_rep;
__device__ double g_ce;
__device__ unsigned int g_cnt;
__device__ double g_acp[TIMESTEPS + 1];
__device__ float d_sa[TIMESTEPS];
__device__ float d_so[TIMESTEPS];
__device__ __align__(16) __nv_bfloat16 gW1T[128 * 72];    // [n][k] pitch 144B
__device__ __align__(16) __nv_bfloat16 gW2T[112 * 136];   // [n][k] pitch 272B

// ---------------------------------------------------------------------------
// helpers
// ---------------------------------------------------------------------------
__device__ __forceinline__ uint32_t smem_u32(const void* p) {
    uint32_t a;
    asm("{ .reg .u64 t; cvta.to.shared.u64 t, %1; cvt.u32.u64 %0, t; }"
        : "=r"(a) : "l"(p));
    return a;
}
__device__ __forceinline__ uint32_t pack_bf16x2(float lo, float hi) {
    uint32_t r;
    asm("cvt.rn.bf16x2.f32 %0, %1, %2;" : "=r"(r) : "f"(hi), "f"(lo));
    return r;
}
__device__ __forceinline__ void ldsm4(uint32_t* r, uint32_t addr) {
    asm volatile("ldmatrix.sync.aligned.m8n8.x4.shared.b16 {%0,%1,%2,%3}, [%4];"
                 : "=r"(r[0]), "=r"(r[1]), "=r"(r[2]), "=r"(r[3]) : "r"(addr));
}
__device__ __forceinline__ void mma_bf16(float* c, const uint32_t* a,
                                         uint32_t b0, uint32_t b1) {
    asm volatile(
        "mma.sync.aligned.m16n8k16.row.col.f32.bf16.bf16.f32 "
        "{%0,%1,%2,%3},{%4,%5,%6,%7},{%8,%9},{%0,%1,%2,%3};"
        : "+f"(c[0]), "+f"(c[1]), "+f"(c[2]), "+f"(c[3])
        : "r"(a[0]), "r"(a[1]), "r"(a[2]), "r"(a[3]), "r"(b0), "r"(b1));
}
__device__ __forceinline__ float tanh_fast(float x) {
    float y;
    asm("tanh.approx.f32 %0, %1;" : "=f"(y) : "f"(x));
    return y;
}
__device__ __forceinline__ float silu_fast(float x) {
    return 0.5f * x * (1.f + tanh_fast(0.5f * x));
}

// ---------------------------------------------------------------------------
// Init (86 blocks x 256): zero accumulators, fp64 cos^2 table (spread across
// SMs), and bf16 weight-image build (one element per thread, no idiv loop).
// ---------------------------------------------------------------------------
__global__ void init_kernel(const float* __restrict__ W1,
                            const float* __restrict__ W2) {
    int i = blockIdx.x * 256 + threadIdx.x;
    if (i == 0) { g_mse = 0.0; g_rep = 0.0; g_ce = 0.0; g_cnt = 0u; }
    if (i <= TIMESTEPS) {
        double x = (double)i;
        double c = cos(((x / 1000.0) + 0.008) / 1.008 * (M_PI * 0.5));
        g_acp[i] = c * c;
    }
    if (i < 8192) {
        int k = i >> 7, n = i & 127;
        gW1T[n * 72 + k] = __float2bfloat16(W1[i]);
    } else if (i < 20992) {
        int i2 = i - 8192;
        int k = i2 / 100, n = i2 - k * 100;
        gW2T[n * 136 + k] = __float2bfloat16(W2[i2]);
    } else if (i < 21808) {
        ((uint32_t*)gW2T)[6800 + (i - 20992)] = 0u;
    }
}

// ---------------------------------------------------------------------------
// fp64 beta + clip + cumprod scan (DMULs only).
// ---------------------------------------------------------------------------
__global__ void scan_kernel() {
    __shared__ double s[1024];
    int i = threadIdx.x;
    double p = 1.0;
    if (i < TIMESTEPS) {
        double beta = 1.0 - g_acp[i + 1] / g_acp[i];
        beta = fmin(fmax(beta, 1e-4), 0.999);
        p = 1.0 - beta;
    }
    s[i] = p;
    __syncthreads();
    for (int off = 1; off < 1024; off <<= 1) {
        double v = (i >= off) ? s[i - off] : 1.0;
        __syncthreads();
        s[i] *= v;
        __syncthreads();
    }
    if (i < TIMESTEPS) {
        double cum = s[i];
        d_sa[i] = (float)sqrt(cum);
        d_so[i] = (float)sqrt(1.0 - cum);
    }
}

// ---------------------------------------------------------------------------
// Fused persistent kernel: species head (tiles) + diffusion/repulsion (tail,
// inverse-balanced) + finalize.
// smem: XB0 @0 (18432), XB1 @18432 (18432), W1T @36864 (18432),
//       W2T @55296 (30464), B1 @85760 (512), B2 @86272 (448), REDD @86720 (64)
// diff-phase scratch reuses [0, ~3.5KB) of XB0 after tiles complete.
// ---------------------------------------------------------------------------
#define OFF_XB0  0
#define XB_SZ    18432
#define OFF_W1T  36864
#define OFF_W2T  55296
#define OFF_B1   85760
#define OFF_B2   86272
#define OFF_REDD 86720
#define SP_SMEM_BYTES 86784
#define P1B 144
#define P2B 272

__global__ void __launch_bounds__(256, 2)
species_kernel(const float* __restrict__ h_final,
               const float* __restrict__ b1,
               const float* __restrict__ b2,
               const int*   __restrict__ species,
               const float* __restrict__ frac,
               const float* __restrict__ noise,
               const float* __restrict__ pred,
               const float* __restrict__ lattice,
               const int*   __restrict__ t,
               float* __restrict__ out) {
    extern __shared__ __align__(16) char smem[];
    uint32_t sb = smem_u32(smem);
    float*  sB1   = (float*)(smem + OFF_B1);
    float*  sB2   = (float*)(smem + OFF_B2);
    double* sRedD = (double*)(smem + OFF_REDD);

    int tid  = threadIdx.x;
    int lane = tid & 31;
    int w    = tid >> 5;
    int g    = lane >> 2;
    int tq   = lane & 3;
    int m0   = w * 16;

    // ---- one-time: copy weight images + biases ----
    {
        const float4* w1i = (const float4*)gW1T;
        float4* d1 = (float4*)(smem + OFF_W1T);
        for (int idx = tid; idx < 1152; idx += 256) d1[idx] = w1i[idx];
        const float4* w2i = (const float4*)gW2T;
        float4* d2 = (float4*)(smem + OFF_W2T);
        for (int idx = tid; idx < 1904; idx += 256) d2[idx] = w2i[idx];
    }
    if (tid < HID) sB1[tid] = b1[tid];
    if (tid < 112) sB2[tid] = (tid < NSP) ? b2[tid] : -1e30f;

    // fragment lane addressing
    int l15 = lane & 15, l7 = lane & 7;
    uint32_t kselA = (uint32_t)((lane >> 4) * 16);
    uint32_t kselB = (uint32_t)(((lane >> 3) & 1) * 16);
    int rB = 8 * (lane >> 4) + l7;

    uint32_t aA1b = sb + OFF_XB0 + (uint32_t)(m0 + l15) * P1B + kselA;
    uint32_t bW1[8];
#pragma unroll
    for (int p = 0; p < 8; p++)
        bW1[p] = sb + OFF_W1T + (uint32_t)(16 * p + rB) * P1B + kselB;
    uint32_t bW2[7];
#pragma unroll
    for (int p = 0; p < 7; p++)
        bW2[p] = sb + OFF_W2T + (uint32_t)(16 * p + rB) * P2B + kselB;

    // ---- prefetch first tile into buffer 0 ----
    {
        int tl = blockIdx.x;
        const float4* gx = (const float4*)(h_final + (size_t)tl * BA * NODE_DIM);
        for (int idx = tid; idx < BA * 16; idx += 256) {
            int m = idx >> 4, kq = idx & 15;
            float4 v = gx[idx];
            uint2 pk = make_uint2(pack_bf16x2(v.x, v.y), pack_bf16x2(v.z, v.w));
            *(uint2*)(smem + OFF_XB0 + m * P1B + kq * 8) = pk;
        }
    }

    double ce_acc = 0.0;
    int pbuf = 0;

    for (int tile = blockIdx.x; tile < NTILES; tile += SGRID) {
        int a0blk = tile * BA;
        __syncthreads();   // fill(cur buf) complete; prior readers of other buf done

        // ================= GEMM1 =================
        float acc1[16][4];
#pragma unroll
        for (int j = 0; j < 16; j++)
#pragma unroll
            for (int q = 0; q < 4; q++) acc1[j][q] = 0.f;

        uint32_t aA1 = aA1b + (uint32_t)(pbuf * XB_SZ);
#pragma unroll
        for (int ks = 0; ks < 4; ks++) {
            uint32_t kb = ks * 32;
            uint32_t af[4];
            ldsm4(af, aA1 + kb);
#pragma unroll
            for (int p = 0; p < 8; p++) {
                uint32_t bf[4];
                ldsm4(bf, bW1[p] + kb);
                mma_bf16(acc1[2 * p],     af, bf[0], bf[1]);
                mma_bf16(acc1[2 * p + 1], af, bf[2], bf[3]);
            }
        }

        // ---- SiLU + bias -> pack into GEMM2 A-fragments ----
        uint32_t hA[8][4];
#pragma unroll
        for (int j = 0; j < 16; j++) {
            int col = 8 * j + 2 * tq;
            float bb0 = sB1[col], bb1 = sB1[col + 1];
            float x0 = silu_fast(acc1[j][0] + bb0);
            float x1 = silu_fast(acc1[j][1] + bb1);
            float x2 = silu_fast(acc1[j][2] + bb0);
            float x3 = silu_fast(acc1[j][3] + bb1);
            hA[j >> 1][(j & 1) * 2 + 0] = pack_bf16x2(x0, x1);
            hA[j >> 1][(j & 1) * 2 + 1] = pack_bf16x2(x2, x3);
        }

        // ---- prefetch next tile into alternate buffer (overlaps GEMM2) ----
        {
            int nxt = tile + SGRID;
            if (nxt < NTILES) {
                const float4* gx = (const float4*)(h_final + (size_t)nxt * BA * NODE_DIM);
                char* base = smem + (pbuf ^ 1) * XB_SZ;
                for (int idx = tid; idx < BA * 16; idx += 256) {
                    int m = idx >> 4, kq = idx & 15;
                    float4 v = gx[idx];
                    uint2 pk = make_uint2(pack_bf16x2(v.x, v.y), pack_bf16x2(v.z, v.w));
                    *(uint2*)(base + m * P1B + kq * 8) = pk;
                }
            }
        }

        // ================= GEMM2 =================
        float acc2[14][4];
#pragma unroll
        for (int j = 0; j < 14; j++)
#pragma unroll
            for (int q = 0; q < 4; q++) acc2[j][q] = 0.f;

#pragma unroll
        for (int ks = 0; ks < 8; ks++) {
            uint32_t kb = ks * 32;
#pragma unroll
            for (int p = 0; p < 7; p++) {
                uint32_t bf[4];
                ldsm4(bf, bW2[p] + kb);
                mma_bf16(acc2[2 * p],     hA[ks], bf[0], bf[1]);
                mma_bf16(acc2[2 * p + 1], hA[ks], bf[2], bf[3]);
            }
        }

        // ---- warp-local softmax + CE ----
        int sp0 = species[a0blk + m0 + g];
        int sp1 = species[a0blk + m0 + g + 8];
        float s0 = 0.f, s1 = 0.f, tg0 = 0.f, tg1 = 0.f;
#pragma unroll
        for (int j = 0; j < 14; j++) {
            int c0 = 8 * j + 2 * tq, c1 = c0 + 1;
            float bb0 = sB2[c0], bb1 = sB2[c1];
            float l00 = acc2[j][0] + bb0;
            float l01 = acc2[j][1] + bb1;
            float l10 = acc2[j][2] + bb0;
            float l11 = acc2[j][3] + bb1;
            s0 += __expf(l00) + __expf(l01);
            s1 += __expf(l10) + __expf(l11);
            if (c0 == sp0) tg0 = l00;
            if (c1 == sp0) tg0 = l01;
            if (c0 == sp1) tg1 = l10;
            if (c1 == sp1) tg1 = l11;
        }
        s0 += __shfl_xor_sync(0xffffffffu, s0, 1);
        s0 += __shfl_xor_sync(0xffffffffu, s0, 2);
        s1 += __shfl_xor_sync(0xffffffffu, s1, 1);
        s1 += __shfl_xor_sync(0xffffffffu, s1, 2);
        tg0 += __shfl_xor_sync(0xffffffffu, tg0, 1);
        tg0 += __shfl_xor_sync(0xffffffffu, tg0, 2);
        tg1 += __shfl_xor_sync(0xffffffffu, tg1, 1);
        tg1 += __shfl_xor_sync(0xffffffffu, tg1, 2);

        float ce = (tq == 0) ? (__logf(s0) - tg0) + (__logf(s1) - tg1) : 0.f;
        ce += __shfl_down_sync(0xffffffffu, ce, 16);
        ce += __shfl_down_sync(0xffffffffu, ce, 8);
        ce += __shfl_down_sync(0xffffffffu, ce, 4);
        if (lane == 0) ce_acc += (double)ce;

        pbuf ^= 1;
    }

    // ================= diff phase (inverse-balanced tail fill) =================
    // CTAs with 4 tiles (b<136) take 4 crystals; 3-tile CTAs take 9-10.
    double dm = 0.0, dr = 0.0;
    {
        int b = blockIdx.x;
        int nc, cstart;
        if (b < 136)      { nc = 4;  cstart = 4 * b; }
        else if (b < 200) { nc = 10; cstart = 544 + 10 * (b - 136); }
        else              { nc = 9;  cstart = 1184 + 9 * (b - 200); }

        float* fsh  = (float*)smem;              // [4][64*3]
        float* Lsh  = (float*)(smem + 3072);     // [4][12]
        float* ssh  = (float*)(smem + 3264);     // [4][2]
        float* redf = (float*)(smem + 3296);     // [8][2]

        int grp = tid >> 6, loc = tid & 63;

        __syncthreads();   // all warps done with tile buffers

        for (int r = 0; r < nc; r += 4) {
            int c = cstart + r + grp;
            bool act = (r + grp) < nc;
            if (act) {
                if (loc == 0) {
                    int tt = t[c];
                    ssh[grp * 2]     = d_sa[tt];
                    ssh[grp * 2 + 1] = d_so[tt];
                }
                if (loc < 9) Lsh[grp * 12 + loc] = lattice[c * 9 + loc];
            }
            __syncthreads();

            float mse = 0.f, rep = 0.f;
            if (act) {
                float sa = ssh[grp * 2], so = ssh[grp * 2 + 1];
                int ga = c * NPER + loc;
#pragma unroll
                for (int d = 0; d < 3; d++) {
                    float fr = frac[ga * 3 + d];
                    float nz = noise[ga * 3 + d];
                    float pn = pred[ga * 3 + d];
                    float xt = sa * fr + so * nz;
                    xt = xt - floorf(xt);
                    float px = (xt - so * pn) / sa;
                    px = px - floorf(px);
                    fsh[grp * 192 + loc * 3 + d] = px;
                    float dd = pn - nz;
                    mse += dd * dd;
                }
            }
            __syncthreads();

            if (act) {
                const float* fg = fsh + grp * 192;
                float fx = fg[loc * 3], fy = fg[loc * 3 + 1], fz = fg[loc * 3 + 2];
                const float* L = Lsh + grp * 12;
                float L00 = L[0], L01 = L[1], L02 = L[2];
                float L10 = L[3], L11 = L[4], L12 = L[5];
                float L20 = L[6], L21 = L[7], L22 = L[8];
#pragma unroll 8
                for (int j = 0; j < NPER; j++) {
                    float dx = fx - fg[j * 3];     dx -= rintf(dx);
                    float dy = fy - fg[j * 3 + 1]; dy -= rintf(dy);
                    float dz = fz - fg[j * 3 + 2]; dz -= rintf(dz);
                    float cx = dx * L00 + dy * L10 + dz * L20;
                    float cy = dx * L01 + dy * L11 + dz * L21;
                    float cz = dx * L02 + dy * L12 + dz * L22;
                    float dsq = cx * cx + cy * cy + cz * cz;
                    if (dsq < 0.64f && j != loc) {
                        float dist = sqrtf(dsq + 1e-8f);
                        float rr = 0.8f - dist;
                        if (rr > 0.f) rep += rr * rr;
                    }
                }
            }
#pragma unroll
            for (int off = 16; off > 0; off >>= 1) {
                mse += __shfl_down_sync(0xffffffffu, mse, off);
                rep += __shfl_down_sync(0xffffffffu, rep, off);
            }
            if (lane == 0) { redf[w * 2] = mse; redf[w * 2 + 1] = rep; }
            __syncthreads();
            if (tid == 0) {
                float sm_ = 0.f, sr_ = 0.f;
#pragma unroll
                for (int i = 0; i < 8; i++) { sm_ += redf[i * 2]; sr_ += redf[i * 2 + 1]; }
                dm += (double)sm_; dr += (double)sr_;
            }
            __syncthreads();
        }
    }

    // ---- CTA reduce + fused finalize ----
    if (lane == 0) sRedD[w] = ce_acc;
    __syncthreads();
    if (tid == 0) {
        double tot = 0.0;
#pragma unroll
        for (int i = 0; i < 8; i++) tot += sRedD[i];
        atomicAdd(&g_ce, tot);
        atomicAdd(&g_mse, dm);
        atomicAdd(&g_rep, dr);
        __threadfence();
        unsigned int v = atomicAdd(&g_cnt, 1u);
        if (v == SGRID - 1) {
            double mse = *((volatile double*)&g_mse);
            double rep = *((volatile double*)&g_rep);
            double cet = *((volatile double*)&g_ce);
            double inv_pairs = 1.0 / ((double)NPER * (double)NB);
            double lrep = rep * inv_pairs;
            out[0] = (float)(mse / (3.0 * (double)NATOMS) + 5.0 * lrep);
            out[1] = (float)(cet / (double)NATOMS);
            out[2] = (float)lrep;
        }
    }
}

// ---------------------------------------------------------------------------
extern "C" void kernel_launch(void* const* d_in, const int* in_sizes, int n_in,
                              void* d_out, int out_size) {
    const float* frac    = (const float*)d_in[0];
    const float* noise   = (const float*)d_in[1];
    const float* pred    = (const float*)d_in[2];
    const float* h_final = (const float*)d_in[3];
    const float* lattice = (const float*)d_in[4];
    const float* W1      = (const float*)d_in[5];
    const float* b1      = (const float*)d_in[6];
    const float* W2      = (const float*)d_in[7];
    const float* b2      = (const float*)d_in[8];
    const int*   t       = (const int*)d_in[9];
    const int*   species = (const int*)d_in[11];
    float* out = (float*)d_out;

    cudaFuncSetAttribute(species_kernel,
                         cudaFuncAttributeMaxDynamicSharedMemorySize,
                         SP_SMEM_BYTES);

    init_kernel<<<86, 256>>>(W1, W2);
    scan_kernel<<<1, 1024>>>();
    species_kernel<<<SGRID, 256, SP_SMEM_BYTES>>>(
        h_final, b1, b2, species, frac, noise, pred, lattice, t, out);
}

// round 12
// speedup vs baseline: 1.2010x; 1.2010x over previous
#include <cuda_runtime.h>
#include <cuda_bf16.h>
#include <math.h>
#include <stdint.h>

#define TIMESTEPS 1000
#define NB 2048
#define NPER 64
#define NATOMS (NB*NPER)
#define NODE_DIM 64
#define HID 128
#define NSP 100
#define BA 128            // atoms per species tile
#define NTILES (NATOMS/BA)
#define SGRID 296         // persistent species grid (148 SMs x 2)

__device__ double g_mse;
__device__ double g_rep;
__device__ double g_ce;
__device__ unsigned int g_cnt;
__device__ double g_acp[TIMESTEPS + 1];
__device__ float d_sa[TIMESTEPS];
__device__ float d_so[TIMESTEPS];
__device__ __align__(16) __nv_bfloat16 gW1T[128 * 72];    // [n][k] pitch 144B
__device__ __align__(16) __nv_bfloat16 gW2T[112 * 136];   // [n][k] pitch 272B

// ---------------------------------------------------------------------------
// helpers
// ---------------------------------------------------------------------------
__device__ __forceinline__ uint32_t smem_u32(const void* p) {
    uint32_t a;
    asm("{ .reg .u64 t; cvta.to.shared.u64 t, %1; cvt.u32.u64 %0, t; }"
        : "=r"(a) : "l"(p));
    return a;
}
__device__ __forceinline__ uint32_t pack_bf16x2(float lo, float hi) {
    uint32_t r;
    asm("cvt.rn.bf16x2.f32 %0, %1, %2;" : "=r"(r) : "f"(hi), "f"(lo));
    return r;
}
__device__ __forceinline__ void ldsm4(uint32_t* r, uint32_t addr) {
    asm volatile("ldmatrix.sync.aligned.m8n8.x4.shared.b16 {%0,%1,%2,%3}, [%4];"
                 : "=r"(r[0]), "=r"(r[1]), "=r"(r[2]), "=r"(r[3]) : "r"(addr));
}
__device__ __forceinline__ void mma_bf16(float* c, const uint32_t* a,
                                         uint32_t b0, uint32_t b1) {
    asm volatile(
        "mma.sync.aligned.m16n8k16.row.col.f32.bf16.bf16.f32 "
        "{%0,%1,%2,%3},{%4,%5,%6,%7},{%8,%9},{%0,%1,%2,%3};"
        : "+f"(c[0]), "+f"(c[1]), "+f"(c[2]), "+f"(c[3])
        : "r"(a[0]), "r"(a[1]), "r"(a[2]), "r"(a[3]), "r"(b0), "r"(b1));
}
__device__ __forceinline__ float tanh_fast(float x) {
    float y;
    asm("tanh.approx.f32 %0, %1;" : "=f"(y) : "f"(x));
    return y;
}
__device__ __forceinline__ float silu_fast(float x) {
    return 0.5f * x * (1.f + tanh_fast(0.5f * x));
}

// ---------------------------------------------------------------------------
// Init (86 blocks x 256): zero accumulators, fp64 cos^2 table spread across
// ALL blocks (j = i/22 -> ~12 cos threads per block), bf16 weight images.
// ---------------------------------------------------------------------------
__global__ void init_kernel(const float* __restrict__ W1,
                            const float* __restrict__ W2) {
    int i = blockIdx.x * 256 + threadIdx.x;
    if (i == 0) { g_mse = 0.0; g_rep = 0.0; g_ce = 0.0; g_cnt = 0u; }
    // spread the fp64 cos chain across every block (latency-parallel)
    if ((i % 22) == 0) {
        int j = i / 22;
        if (j <= TIMESTEPS) {
            double x = (double)j;
            double c = cos(((x / 1000.0) + 0.008) / 1.008 * (M_PI * 0.5));
            g_acp[j] = c * c;
        }
    }
    if (i < 8192) {
        int k = i >> 7, n = i & 127;
        gW1T[n * 72 + k] = __float2bfloat16(W1[i]);
    } else if (i < 20992) {
        int i2 = i - 8192;
        int k = i2 / 100, n = i2 - k * 100;
        gW2T[n * 136 + k] = __float2bfloat16(W2[i2]);
    } else if (i < 21808) {
        ((uint32_t*)gW2T)[6800 + (i - 20992)] = 0u;
    }
}

// ---------------------------------------------------------------------------
// fp64 beta + clip + cumprod scan (DMULs only).
// ---------------------------------------------------------------------------
__global__ void scan_kernel() {
    __shared__ double s[1024];
    int i = threadIdx.x;
    double p = 1.0;
    if (i < TIMESTEPS) {
        double beta = 1.0 - g_acp[i + 1] / g_acp[i];
        beta = fmin(fmax(beta, 1e-4), 0.999);
        p = 1.0 - beta;
    }
    s[i] = p;
    __syncthreads();
    for (int off = 1; off < 1024; off <<= 1) {
        double v = (i >= off) ? s[i - off] : 1.0;
        __syncthreads();
        s[i] *= v;
        __syncthreads();
    }
    if (i < TIMESTEPS) {
        double cum = s[i];
        d_sa[i] = (float)sqrt(cum);
        d_so[i] = (float)sqrt(1.0 - cum);
    }
}

// ---------------------------------------------------------------------------
// Diffusion MSE + PBC repulsion: one block per crystal (64 atoms).
// ---------------------------------------------------------------------------
__global__ void diff_kernel(const float* __restrict__ frac,
                            const float* __restrict__ noise,
                            const float* __restrict__ pred,
                            const float* __restrict__ lattice,
                            const int*   __restrict__ t) {
    __shared__ float f[NPER][3];
    __shared__ float L[9];
    __shared__ float ss[2];
    __shared__ float red[4];

    int b = blockIdx.x;
    int tid = threadIdx.x;
    int ga = b * NPER + tid;

    if (tid == 0) {
        int tt = t[b];
        ss[0] = d_sa[tt];
        ss[1] = d_so[tt];
    }
    if (tid < 9) L[tid] = lattice[b * 9 + tid];
    __syncthreads();

    float sa = ss[0], so = ss[1];

    float mse = 0.f;
#pragma unroll
    for (int d = 0; d < 3; d++) {
        float fr = frac[ga * 3 + d];
        float nz = noise[ga * 3 + d];
        float pn = pred[ga * 3 + d];
        float xt = sa * fr + so * nz;
        xt = xt - floorf(xt);
        float px = (xt - so * pn) / sa;
        px = px - floorf(px);
        f[tid][d] = px;
        float dd = pn - nz;
        mse += dd * dd;
    }
    __syncthreads();

    float fx = f[tid][0], fy = f[tid][1], fz = f[tid][2];
    float L00 = L[0], L01 = L[1], L02 = L[2];
    float L10 = L[3], L11 = L[4], L12 = L[5];
    float L20 = L[6], L21 = L[7], L22 = L[8];

    float rep = 0.f;
#pragma unroll 8
    for (int j = 0; j < NPER; j++) {
        float dx = fx - f[j][0]; dx -= rintf(dx);
        float dy = fy - f[j][1]; dy -= rintf(dy);
        float dz = fz - f[j][2]; dz -= rintf(dz);
        float cx = dx * L00 + dy * L10 + dz * L20;
        float cy = dx * L01 + dy * L11 + dz * L21;
        float cz = dx * L02 + dy * L12 + dz * L22;
        float dsq = cx * cx + cy * cy + cz * cz;
        if (dsq < 0.64f && j != tid) {
            float dist = sqrtf(dsq + 1e-8f);
            float r = 0.8f - dist;
            if (r > 0.f) rep += r * r;
        }
    }

#pragma unroll
    for (int off = 16; off > 0; off >>= 1) {
        mse += __shfl_down_sync(0xffffffffu, mse, off);
        rep += __shfl_down_sync(0xffffffffu, rep, off);
    }
    if ((tid & 31) == 0) {
        red[(tid >> 5) * 2]     = mse;
        red[(tid >> 5) * 2 + 1] = rep;
    }
    __syncthreads();
    if (tid == 0) {
        atomicAdd(&g_mse, (double)(red[0] + red[2]));
        atomicAdd(&g_rep, (double)(red[1] + red[3]));
    }
}

// ---------------------------------------------------------------------------
// Species head: persistent CTAs, bf16 mma.sync m16n8k16, register-chained.
// (byte-identical to the 61.5us R10 version)
// ---------------------------------------------------------------------------
#define OFF_XB   0
#define OFF_W1T  18432
#define OFF_W2T  36864
#define OFF_B1   67328
#define OFF_B2   67840
#define OFF_REDD 68288
#define SP_SMEM_BYTES 68352
#define P1B 144
#define P2B 272

__global__ void __launch_bounds__(256, 2)
species_kernel(const float* __restrict__ h_final,
               const float* __restrict__ b1,
               const float* __restrict__ b2,
               const int*   __restrict__ species,
               float* __restrict__ out) {
    extern __shared__ __align__(16) char smem[];
    uint32_t sb = smem_u32(smem);
    float*  sB1   = (float*)(smem + OFF_B1);
    float*  sB2   = (float*)(smem + OFF_B2);
    double* sRedD = (double*)(smem + OFF_REDD);

    int tid  = threadIdx.x;
    int lane = tid & 31;
    int w    = tid >> 5;
    int g    = lane >> 2;
    int t    = lane & 3;
    int m0   = w * 16;

    {
        const float4* w1i = (const float4*)gW1T;
        float4* d1 = (float4*)(smem + OFF_W1T);
        for (int idx = tid; idx < 1152; idx += 256) d1[idx] = w1i[idx];
        const float4* w2i = (const float4*)gW2T;
        float4* d2 = (float4*)(smem + OFF_W2T);
        for (int idx = tid; idx < 1904; idx += 256) d2[idx] = w2i[idx];
    }
    if (tid < HID) sB1[tid] = b1[tid];
    if (tid < 112) sB2[tid] = (tid < NSP) ? b2[tid] : -1e30f;
    __syncthreads();

    int l15 = lane & 15, l7 = lane & 7;
    uint32_t kselA = (uint32_t)((lane >> 4) * 16);
    uint32_t kselB = (uint32_t)(((lane >> 3) & 1) * 16);
    int rB = 8 * (lane >> 4) + l7;

    uint32_t aA1 = sb + OFF_XB + (uint32_t)(m0 + l15) * P1B + kselA;
    uint32_t bW1[8];
#pragma unroll
    for (int p = 0; p < 8; p++)
        bW1[p] = sb + OFF_W1T + (uint32_t)(16 * p + rB) * P1B + kselB;
    uint32_t bW2[7];
#pragma unroll
    for (int p = 0; p < 7; p++)
        bW2[p] = sb + OFF_W2T + (uint32_t)(16 * p + rB) * P2B + kselB;

    double ce_acc = 0.0;

    for (int tile = blockIdx.x; tile < NTILES; tile += SGRID) {
        int a0blk = tile * BA;

        {
            const float4* gx = (const float4*)(h_final + (size_t)a0blk * NODE_DIM);
            for (int idx = tid; idx < BA * 16; idx += 256) {
                int m = idx >> 4, kq = idx & 15;
                float4 v = gx[idx];
                uint2 pk = make_uint2(pack_bf16x2(v.x, v.y), pack_bf16x2(v.z, v.w));
                *(uint2*)(smem + OFF_XB + m * P1B + kq * 8) = pk;
            }
        }
        __syncthreads();

        float acc1[16][4];
#pragma unroll
        for (int j = 0; j < 16; j++)
#pragma unroll
            for (int q = 0; q < 4; q++) acc1[j][q] = 0.f;

#pragma unroll
        for (int ks = 0; ks < 4; ks++) {
            uint32_t kb = ks * 32;
            uint32_t af[4];
            ldsm4(af, aA1 + kb);
#pragma unroll
            for (int p = 0; p < 8; p++) {
                uint32_t bf[4];
                ldsm4(bf, bW1[p] + kb);
                mma_bf16(acc1[2 * p],     af, bf[0], bf[1]);
                mma_bf16(acc1[2 * p + 1], af, bf[2], bf[3]);
            }
        }
        __syncthreads();

        uint32_t hA[8][4];
#pragma unroll
        for (int j = 0; j < 16; j++) {
            int col = 8 * j + 2 * t;
            float bb0 = sB1[col], bb1 = sB1[col + 1];
            float x0 = silu_fast(acc1[j][0] + bb0);
            float x1 = silu_fast(acc1[j][1] + bb1);
            float x2 = silu_fast(acc1[j][2] + bb0);
            float x3 = silu_fast(acc1[j][3] + bb1);
            hA[j >> 1][(j & 1) * 2 + 0] = pack_bf16x2(x0, x1);
            hA[j >> 1][(j & 1) * 2 + 1] = pack_bf16x2(x2, x3);
        }

        float acc2[14][4];
#pragma unroll
        for (int j = 0; j < 14; j++)
#pragma unroll
            for (int q = 0; q < 4; q++) acc2[j][q] = 0.f;

#pragma unroll
        for (int ks = 0; ks < 8; ks++) {
            uint32_t kb = ks * 32;
#pragma unroll
            for (int p = 0; p < 7; p++) {
                uint32_t bf[4];
                ldsm4(bf, bW2[p] + kb);
                mma_bf16(acc2[2 * p],     hA[ks], bf[0], bf[1]);
                mma_bf16(acc2[2 * p + 1], hA[ks], bf[2], bf[3]);
            }
        }

        int sp0 = species[a0blk + m0 + g];
        int sp1 = species[a0blk + m0 + g + 8];
        float s0 = 0.f, s1 = 0.f, tg0 = 0.f, tg1 = 0.f;
#pragma unroll
        for (int j = 0; j < 14; j++) {
            int c0 = 8 * j + 2 * t, c1 = c0 + 1;
            float bb0 = sB2[c0], bb1 = sB2[c1];
            float l00 = acc2[j][0] + bb0;
            float l01 = acc2[j][1] + bb1;
            float l10 = acc2[j][2] + bb0;
            float l11 = acc2[j][3] + bb1;
            s0 += __expf(l00) + __expf(l01);
            s1 += __expf(l10) + __expf(l11);
            if (c0 == sp0) tg0 = l00;
            if (c1 == sp0) tg0 = l01;
            if (c0 == sp1) tg1 = l10;
            if (c1 == sp1) tg1 = l11;
        }
        s0 += __shfl_xor_sync(0xffffffffu, s0, 1);
        s0 += __shfl_xor_sync(0xffffffffu, s0, 2);
        s1 += __shfl_xor_sync(0xffffffffu, s1, 1);
        s1 += __shfl_xor_sync(0xffffffffu, s1, 2);
        tg0 += __shfl_xor_sync(0xffffffffu, tg0, 1);
        tg0 += __shfl_xor_sync(0xffffffffu, tg0, 2);
        tg1 += __shfl_xor_sync(0xffffffffu, tg1, 1);
        tg1 += __shfl_xor_sync(0xffffffffu, tg1, 2);

        float ce = (t == 0) ? (__logf(s0) - tg0) + (__logf(s1) - tg1) : 0.f;
        ce += __shfl_down_sync(0xffffffffu, ce, 16);
        ce += __shfl_down_sync(0xffffffffu, ce, 8);
        ce += __shfl_down_sync(0xffffffffu, ce, 4);
        if (lane == 0) ce_acc += (double)ce;
    }

    if (lane == 0) sRedD[w] = ce_acc;
    __syncthreads();
    if (tid == 0) {
        double tot = 0.0;
#pragma unroll
        for (int i = 0; i < 8; i++) tot += sRedD[i];
        atomicAdd(&g_ce, tot);
        __threadfence();
        unsigned int v = atomicAdd(&g_cnt, 1u);
        if (v == SGRID - 1) {
            double mse = *((volatile double*)&g_mse);
            double rep = *((volatile double*)&g_rep);
            double cet = *((volatile double*)&g_ce);
            double inv_pairs = 1.0 / ((double)NPER * (double)NB);
            double lrep = rep * inv_pairs;
            out[0] = (float)(mse / (3.0 * (double)NATOMS) + 5.0 * lrep);
            out[1] = (float)(cet / (double)NATOMS);
            out[2] = (float)lrep;
        }
    }
}

// ---------------------------------------------------------------------------
extern "C" void kernel_launch(void* const* d_in, const int* in_sizes, int n_in,
                              void* d_out, int out_size) {
    const float* frac    = (const float*)d_in[0];
    const float* noise   = (const float*)d_in[1];
    const float* pred    = (const float*)d_in[2];
    const float* h_final = (const float*)d_in[3];
    const float* lattice = (const float*)d_in[4];
    const float* W1      = (const float*)d_in[5];
    const float* b1      = (const float*)d_in[6];
    const float* W2      = (const float*)d_in[7];
    const float* b2      = (const float*)d_in[8];
    const int*   t       = (const int*)d_in[9];
    const int*   species = (const int*)d_in[11];
    float* out = (float*)d_out;

    cudaFuncSetAttribute(species_kernel,
                         cudaFuncAttributeMaxDynamicSharedMemorySize,
                         SP_SMEM_BYTES);

    init_kernel<<<86, 256>>>(W1, W2);
    scan_kernel<<<1, 1024>>>();
    diff_kernel<<<NB, NPER>>>(frac, noise, pred, lattice, t);
    species_kernel<<<SGRID, 256, SP_SMEM_BYTES>>>(h_final, b1, b2, species, out);
}